// round 3
// baseline (speedup 1.0000x reference)
#include <cuda_runtime.h>

// db2 inverse DWT (synthesis), polyphase. 2 input cols x 2 input rows per thread.
// x: [32, 512, 512, 4] NHWC f32  ->  y: [32, 1024, 1024, 1] f32

#define IN_H 512
#define IN_W 512
#define IN_B 32

__global__ __launch_bounds__(128)
void idwt_db2_kernel(const float4* __restrict__ x, float4* __restrict__ y) {
    const int u  = blockIdx.x * blockDim.x + threadIdx.x;  // 0..255 (col pair)
    const int sg = blockIdx.y;                             // 0..255 (row pair)
    const int b  = blockIdx.z;                             // 0..31

    const float h0 = 0.48296291314469025f;
    const float h1 = 0.83651630373780790f;
    const float h2 = 0.22414386804185735f;
    const float h3 = -0.12940952255092145f;
    // lpf = {h3,h2,h1,h0} -> L[0]={h2,h0}, L[1]={h3,h1}
    // hpf = {-h0,h1,-h2,h3} -> G[0]={h1,h3}, G[1]={-h0,-h2}
    const float L[2][2] = { { h2,  h0 }, {  h3,  h1 } };
    const float G[2][2] = { { h1,  h3 }, { -h0, -h2 } };

    const int t0 = 2 * u;
    const int t1 = 2 * u + 1;
    const int t2 = min(2 * u + 2, IN_W - 1);
    const int s0 = 2 * sg;
    const int s1 = 2 * sg + 1;
    const int s2 = min(2 * sg + 2, IN_H - 1);

    const size_t base = (size_t)b * IN_H * IN_W;
    const size_t r0 = base + (size_t)s0 * IN_W;
    const size_t r1 = base + (size_t)s1 * IN_W;
    const size_t r2 = base + (size_t)s2 * IN_W;

    // 9 independent 16B loads, all issued up front (MLP=9)
    float4 V[3][3];
    V[0][0] = __ldg(&x[r0 + t0]); V[0][1] = __ldg(&x[r0 + t1]); V[0][2] = __ldg(&x[r0 + t2]);
    V[1][0] = __ldg(&x[r1 + t0]); V[1][1] = __ldg(&x[r1 + t1]); V[1][2] = __ldg(&x[r1 + t2]);
    V[2][0] = __ldg(&x[r2 + t0]); V[2][1] = __ldg(&x[r2 + t1]); V[2][2] = __ldg(&x[r2 + t2]);

    // Horizontal pass per input row: 4 output columns each.
    // hA: (c0+c1 channel, L filters) + (c2 channel, G horizontal filter) combined
    // hW: c3 channel (G filters both dims)
    float hA[3][4], hW[3][4];
#pragma unroll
    for (int i = 0; i < 3; ++i) {
        float aL = V[i][0].x + V[i][0].y;
        float aM = V[i][1].x + V[i][1].y;
        float aR = V[i][2].x + V[i][2].y;
        float zL = V[i][0].z, zM = V[i][1].z, zR = V[i][2].z;
        float wL = V[i][0].w, wM = V[i][1].w, wR = V[i][2].w;
#pragma unroll
        for (int ah = 0; ah < 2; ++ah) {
            // output cols 4u+ah from (left=c0, right=c1)
            float r = L[ah][0] * aL;
            r = fmaf(L[ah][1], aM, r);
            r = fmaf(G[ah][0], zL, r);
            r = fmaf(G[ah][1], zM, r);
            hA[i][ah] = r;
            hW[i][ah] = fmaf(G[ah][0], wL, G[ah][1] * wM);
            // output cols 4u+2+ah from (left=c1, right=c2)
            float r2v = L[ah][0] * aM;
            r2v = fmaf(L[ah][1], aR, r2v);
            r2v = fmaf(G[ah][0], zM, r2v);
            r2v = fmaf(G[ah][1], zR, r2v);
            hA[i][2 + ah] = r2v;
            hW[i][2 + ah] = fmaf(G[ah][0], wM, G[ah][1] * wR);
        }
    }

    // Vertical pass: 4 output rows (2*s0 .. 2*s0+3), 1 float4 each.
    const size_t ob = ((size_t)b * 1024 + (size_t)4 * sg) * 256 + u;
#pragma unroll
    for (int rp = 0; rp < 2; ++rp) {          // input row pair (rp, rp+1)
#pragma unroll
        for (int av = 0; av < 2; ++av) {
            float o[4];
#pragma unroll
            for (int j = 0; j < 4; ++j) {
                float r = L[av][0] * hA[rp][j];
                r = fmaf(L[av][1], hA[rp + 1][j], r);
                r = fmaf(G[av][0], hW[rp][j], r);
                r = fmaf(G[av][1], hW[rp + 1][j], r);
                o[j] = r;
            }
            y[ob + (size_t)(2 * rp + av) * 256] = make_float4(o[0], o[1], o[2], o[3]);
        }
    }
}

extern "C" void kernel_launch(void* const* d_in, const int* in_sizes, int n_in,
                              void* d_out, int out_size) {
    const float4* x = (const float4*)d_in[0];
    float4* y = (float4*)d_out;
    dim3 block(128, 1, 1);
    dim3 grid((IN_W / 2) / 128, IN_H / 2, IN_B);
    idwt_db2_kernel<<<grid, block>>>(x, y);
}

// round 4
// speedup vs baseline: 1.0125x; 1.0125x over previous
#include <cuda_runtime.h>

// db2 inverse DWT (synthesis), polyphase form, 2 input cols per thread.
// x: [32, 512, 512, 4] NHWC f32  ->  y: [32, 1024, 1024, 1] f32
// R2 decomposition (best DRAM%), plus streaming stores + 256-thread blocks.

#define IN_H 512
#define IN_W 512
#define IN_B 32

__device__ __forceinline__ void quad2x2(
    const float4& v00, const float4& v01,
    const float4& v10, const float4& v11,
    const float L[2][2], const float G[2][2],
    float out[2][2])
{
    float a0[2] = { v00.x + v00.y, v10.x + v10.y };
    float a1[2] = { v01.x + v01.y, v11.x + v11.y };
    float z0[2] = { v00.z, v10.z };
    float z1[2] = { v01.z, v11.z };
    float w0[2] = { v00.w, v10.w };
    float w1[2] = { v01.w, v11.w };

    float r_az[2][2], r_w[2][2];
#pragma unroll
    for (int dv = 0; dv < 2; ++dv) {
#pragma unroll
        for (int ah = 0; ah < 2; ++ah) {
            float r = L[ah][0] * a0[dv];
            r = fmaf(L[ah][1], a1[dv], r);
            r = fmaf(G[ah][0], z0[dv], r);
            r = fmaf(G[ah][1], z1[dv], r);
            r_az[dv][ah] = r;
            r_w[dv][ah] = fmaf(G[ah][0], w0[dv], G[ah][1] * w1[dv]);
        }
    }
#pragma unroll
    for (int av = 0; av < 2; ++av) {
#pragma unroll
        for (int ah = 0; ah < 2; ++ah) {
            float r = L[av][0] * r_az[0][ah];
            r = fmaf(L[av][1], r_az[1][ah], r);
            r = fmaf(G[av][0], r_w[0][ah], r);
            r = fmaf(G[av][1], r_w[1][ah], r);
            out[av][ah] = r;
        }
    }
}

__device__ __forceinline__ void stcs4(float4* p, float4 v) {
    asm volatile("st.global.cs.v4.f32 [%0], {%1,%2,%3,%4};"
                 :: "l"(p), "f"(v.x), "f"(v.y), "f"(v.z), "f"(v.w) : "memory");
}

__global__ __launch_bounds__(256)
void idwt_db2_kernel(const float4* __restrict__ x, float4* __restrict__ y) {
    const int uu = blockIdx.x * blockDim.x + threadIdx.x;  // 0..(256*512-1)
    const int u  = uu & 255;                               // 0..255 (col pair)
    const int s  = uu >> 8;                                // 0..511 (input row)
    const int b  = blockIdx.z;                             // 0..31

    const float h0 = 0.48296291314469025f;
    const float h1 = 0.83651630373780790f;
    const float h2 = 0.22414386804185735f;
    const float h3 = -0.12940952255092145f;
    const float L[2][2] = { { h2,  h0 }, {  h3,  h1 } };
    const float G[2][2] = { { h1,  h3 }, { -h0, -h2 } };

    const int t0 = 2 * u;
    const int t1 = 2 * u + 1;
    const int t2 = min(2 * u + 2, IN_W - 1);
    const int s1 = min(s + 1, IN_H - 1);

    const size_t r0 = ((size_t)b * IN_H + s ) * IN_W;
    const size_t r1 = ((size_t)b * IN_H + s1) * IN_W;

    // 6 independent 16B loads, issued up front
    const float4 A0 = __ldg(&x[r0 + t0]);
    const float4 A1 = __ldg(&x[r0 + t1]);
    const float4 A2 = __ldg(&x[r0 + t2]);
    const float4 B0 = __ldg(&x[r1 + t0]);
    const float4 B1 = __ldg(&x[r1 + t1]);
    const float4 B2 = __ldg(&x[r1 + t2]);

    float oA[2][2], oB[2][2];
    quad2x2(A0, A1, B0, B1, L, G, oA);   // out cols 4u..4u+1
    quad2x2(A1, A2, B1, B2, L, G, oB);   // out cols 4u+2..4u+3

    const size_t ob = ((size_t)b * 1024 + 2 * s) * 256 + u;
    stcs4(&y[ob],       make_float4(oA[0][0], oA[0][1], oB[0][0], oB[0][1]));
    stcs4(&y[ob + 256], make_float4(oA[1][0], oA[1][1], oB[1][0], oB[1][1]));
}

extern "C" void kernel_launch(void* const* d_in, const int* in_sizes, int n_in,
                              void* d_out, int out_size) {
    const float4* x = (const float4*)d_in[0];
    float4* y = (float4*)d_out;
    dim3 block(256, 1, 1);
    dim3 grid((256 * 512) / 256, 1, IN_B);
    idwt_db2_kernel<<<grid, block>>>(x, y);
}